// round 1
// baseline (speedup 1.0000x reference)
#include <cuda_runtime.h>
#include <math.h>

#define BATCH 4096
#define DIM 1024
#define NC 100000
#define NS 5000
#define NS_PAD 5120
#define NTN 40            // ceil(5000/128) N-tiles
#define LSE_OFF 20.0f

#define BM 128
#define BN 128
#define BK 8

// Device scratch (no allocations allowed in kernel_launch)
__device__ float g_ws[(size_t)NS_PAD * DIM];          // gathered w[:, sampled], [s][d]
__device__ float g_soff[NS_PAD];                      // b[sampled] - log_expected_count(sampled)
__device__ float g_true[BATCH];                       // adjusted true logits
__device__ float g_partial[BATCH * (NTN + 1)];        // per-(row, n-tile) exp-sum partials; slot NTN = true term

__device__ __forceinline__ float log_expected_count(int c) {
    float cf = (float)c;
    float p = logf((cf + 2.0f) / (cf + 1.0f)) / logf((float)NC + 1.0f);
    return logf(-expm1f((float)NS * log1pf(-p)));
}

// ---------------------------------------------------------------------------
// Kernel 1: gather sampled columns of w into K-major scratch + per-col offset
// ---------------------------------------------------------------------------
__global__ void gather_kernel(const float* __restrict__ w,
                              const float* __restrict__ b,
                              const int* __restrict__ sampled) {
    int s = blockIdx.x;
    if (s < NS) {
        int c = sampled[s];
        const float* wc = w + c;
        for (int d = threadIdx.x; d < DIM; d += blockDim.x)
            g_ws[(size_t)s * DIM + d] = wc[(size_t)d * NC];
        if (threadIdx.x == 0)
            g_soff[s] = b[c] - log_expected_count(c);
    } else {
        for (int d = threadIdx.x; d < DIM; d += blockDim.x)
            g_ws[(size_t)s * DIM + d] = 0.0f;
        if (threadIdx.x == 0)
            g_soff[s] = 0.0f;
    }
}

// ---------------------------------------------------------------------------
// Kernel 2: true logits (one warp per batch row) + seed the row exp-sum
// ---------------------------------------------------------------------------
__global__ void true_kernel(const float* __restrict__ x,
                            const float* __restrict__ w,
                            const float* __restrict__ b,
                            const int* __restrict__ labels) {
    int r = blockIdx.x * 8 + (threadIdx.x >> 5);
    int lane = threadIdx.x & 31;
    if (r >= BATCH) return;
    int c = labels[r];
    const float* xr = x + (size_t)r * DIM;
    const float* wc = w + c;
    float s = 0.0f;
    for (int d = lane; d < DIM; d += 32)
        s += xr[d] * wc[(size_t)d * NC];
    #pragma unroll
    for (int o = 16; o; o >>= 1)
        s += __shfl_xor_sync(0xffffffffu, s, o);
    if (lane == 0) {
        float t = s + b[c] - log_expected_count(c);
        g_true[r] = t;
        g_partial[r * (NTN + 1) + NTN] = expf(t - LSE_OFF);
    }
}

// ---------------------------------------------------------------------------
// Kernel 3: 128x128x8 SGEMM, fused exp-sum epilogue (per row, per n-tile)
// ---------------------------------------------------------------------------
__global__ __launch_bounds__(256, 2)
void gemm_lse_kernel(const float* __restrict__ x) {
    __shared__ float As[BK][BM];
    __shared__ float Bs[BK][BN];

    int bn = blockIdx.x;          // n-tile
    int bm = blockIdx.y;          // m-tile
    int tid = threadIdx.x;
    int tx = tid & 15;
    int ty = tid >> 4;
    int m0 = bm * BM;
    int n0 = bn * BN;

    float acc[8][8];
    #pragma unroll
    for (int i = 0; i < 8; i++)
        #pragma unroll
        for (int j = 0; j < 8; j++) acc[i][j] = 0.0f;

    int lrow = tid >> 1;            // 0..127
    int lk4  = (tid & 1) * 4;       // 0 or 4
    const float* aptr = x + (size_t)(m0 + lrow) * DIM + lk4;
    const float* bptr = g_ws + (size_t)(n0 + lrow) * DIM + lk4;

    for (int kk = 0; kk < DIM; kk += BK) {
        float4 av = *(const float4*)(aptr + kk);
        float4 bv = *(const float4*)(bptr + kk);
        __syncthreads();
        As[lk4 + 0][lrow] = av.x;
        As[lk4 + 1][lrow] = av.y;
        As[lk4 + 2][lrow] = av.z;
        As[lk4 + 3][lrow] = av.w;
        Bs[lk4 + 0][lrow] = bv.x;
        Bs[lk4 + 1][lrow] = bv.y;
        Bs[lk4 + 2][lrow] = bv.z;
        Bs[lk4 + 3][lrow] = bv.w;
        __syncthreads();

        #pragma unroll
        for (int k = 0; k < BK; k++) {
            float a[8], b[8];
            float4 a0 = *(const float4*)&As[k][ty * 4];
            float4 a1 = *(const float4*)&As[k][64 + ty * 4];
            float4 b0 = *(const float4*)&Bs[k][tx * 4];
            float4 b1 = *(const float4*)&Bs[k][64 + tx * 4];
            a[0] = a0.x; a[1] = a0.y; a[2] = a0.z; a[3] = a0.w;
            a[4] = a1.x; a[5] = a1.y; a[6] = a1.z; a[7] = a1.w;
            b[0] = b0.x; b[1] = b0.y; b[2] = b0.z; b[3] = b0.w;
            b[4] = b1.x; b[5] = b1.y; b[6] = b1.z; b[7] = b1.w;
            #pragma unroll
            for (int i = 0; i < 8; i++)
                #pragma unroll
                for (int j = 0; j < 8; j++)
                    acc[i][j] = fmaf(a[i], b[j], acc[i][j]);
        }
    }

    // Per-column offsets (bias - log_expected_count), hoisted
    float soff[8];
    int colg[8];
    #pragma unroll
    for (int j = 0; j < 8; j++) {
        int c = (j < 4) ? (tx * 4 + j) : (64 + tx * 4 + (j - 4));
        colg[j] = n0 + c;
        soff[j] = g_soff[colg[j]];
    }

    // Per-row exp-sum, reduced across the 16 tx lanes
    #pragma unroll
    for (int i = 0; i < 8; i++) {
        int row = (i < 4) ? (ty * 4 + i) : (64 + ty * 4 + (i - 4));
        float sum = 0.0f;
        #pragma unroll
        for (int j = 0; j < 8; j++) {
            if (colg[j] < NS)
                sum += expf(acc[i][j] + soff[j] - LSE_OFF);
        }
        #pragma unroll
        for (int o = 1; o < 16; o <<= 1)
            sum += __shfl_xor_sync(0xffffffffu, sum, o);
        if (tx == 0)
            g_partial[(m0 + row) * (NTN + 1) + bn] = sum;
    }
}

// ---------------------------------------------------------------------------
// Kernel 4: final reduction -> mean loss
// ---------------------------------------------------------------------------
__global__ void final_kernel(float* __restrict__ out) {
    __shared__ float red[256];
    float acc = 0.0f;
    for (int r = threadIdx.x; r < BATCH; r += 256) {
        float s = 0.0f;
        #pragma unroll 8
        for (int t = 0; t <= NTN; t++)
            s += g_partial[r * (NTN + 1) + t];
        acc += LSE_OFF + logf(s) - g_true[r];
    }
    red[threadIdx.x] = acc;
    __syncthreads();
    for (int st = 128; st; st >>= 1) {
        if (threadIdx.x < st) red[threadIdx.x] += red[threadIdx.x + st];
        __syncthreads();
    }
    if (threadIdx.x == 0)
        out[0] = red[0] / (float)BATCH;
}

// ---------------------------------------------------------------------------
extern "C" void kernel_launch(void* const* d_in, const int* in_sizes, int n_in,
                              void* d_out, int out_size) {
    const float* x       = (const float*)d_in[0];
    const float* w       = (const float*)d_in[1];
    const float* b       = (const float*)d_in[2];
    const int*   labels  = (const int*)d_in[3];
    const int*   sampled = (const int*)d_in[4];
    float* out = (float*)d_out;

    gather_kernel<<<NS_PAD, 256>>>(w, b, sampled);
    true_kernel<<<BATCH / 8, 256>>>(x, w, b, labels);
    dim3 grid(NTN, BATCH / BM);
    gemm_lse_kernel<<<grid, 256>>>(x);
    final_kernel<<<1, 256>>>(out);
}

// round 3
// speedup vs baseline: 2.2379x; 2.2379x over previous
#include <cuda_runtime.h>
#include <cuda_bf16.h>
#include <math.h>
#include <stdint.h>

#define BATCH 4096
#define DIM 1024
#define NC 100000
#define NS 5000
#define NS_PAD 5120
#define LSE_OFF 20.0f

// GEMM: K split into 3 segments (hi*hi + hi*lo + lo*hi), single K=3072 GEMM
#define KTOT 3072
#define TM 128
#define TN 128
#define TK 64
#define NKT (KTOT / TK)          // 48
#define NTN (NS_PAD / TN)        // 40 n-tiles
#define NSLOT (NTN * 4 + 1)      // one slot per (n-tile, n-warp) + true slot

// ---------------------------------------------------------------------------
// Device scratch
// ---------------------------------------------------------------------------
__device__ __nv_bfloat16 g_a[(size_t)BATCH * KTOT];    // [Ahi | Ahi | Alo]
__device__ __nv_bfloat16 g_b[(size_t)NS_PAD * KTOT];   // [Bhi | Blo | Bhi]
__device__ float g_soff[NS_PAD];
__device__ float g_true[BATCH];
__device__ float g_partial[BATCH * NSLOT];
__device__ float g_fin[32];

// ---------------------------------------------------------------------------
// PTX helpers (family-portable only: sm_80-class instructions)
// ---------------------------------------------------------------------------
__device__ __forceinline__ uint32_t smem_u32(const void* p) {
    uint32_t a;
    asm("{ .reg .u64 t; cvta.to.shared.u64 t, %1; cvt.u32.u64 %0, t; }" : "=r"(a) : "l"(p));
    return a;
}
#define CP_ASYNC16(dst, src) \
    asm volatile("cp.async.cg.shared.global [%0], [%1], 16;" :: "r"(dst), "l"(src))
#define CP_COMMIT() asm volatile("cp.async.commit_group;" ::: "memory")
#define CP_WAIT1()  asm volatile("cp.async.wait_group 1;" ::: "memory")
#define CP_WAIT0()  asm volatile("cp.async.wait_group 0;" ::: "memory")

#define LDSM_X4(r0, r1, r2, r3, addr) \
    asm volatile("ldmatrix.sync.aligned.m8n8.x4.shared.b16 {%0,%1,%2,%3}, [%4];" \
        : "=r"(r0), "=r"(r1), "=r"(r2), "=r"(r3) : "r"(addr))

#define MMA16816(d, a, b) \
    asm volatile("mma.sync.aligned.m16n8k16.row.col.f32.bf16.bf16.f32 " \
        "{%0,%1,%2,%3}, {%4,%5,%6,%7}, {%8,%9}, {%0,%1,%2,%3};" \
        : "+f"((d)[0]), "+f"((d)[1]), "+f"((d)[2]), "+f"((d)[3]) \
        : "r"((a)[0]), "r"((a)[1]), "r"((a)[2]), "r"((a)[3]), "r"((b)[0]), "r"((b)[1]))

__device__ __forceinline__ float log_expected_count(int c) {
    float cf = (float)c;
    float p = logf((cf + 2.0f) / (cf + 1.0f)) / logf((float)NC + 1.0f);
    return logf(-expm1f((float)NS * log1pf(-p)));
}

// ---------------------------------------------------------------------------
// Kernel 1: convert x -> bf16 split layout [hi | hi | lo]
// ---------------------------------------------------------------------------
__global__ void convert_x_kernel(const float* __restrict__ x) {
    int r = blockIdx.x;
    const float* xr = x + (size_t)r * DIM;
    __nv_bfloat16* ar = g_a + (size_t)r * KTOT;
    for (int d = threadIdx.x; d < DIM; d += 256) {
        float v = xr[d];
        __nv_bfloat16 hi = __float2bfloat16(v);
        __nv_bfloat16 lo = __float2bfloat16(v - __bfloat162float(hi));
        ar[d] = hi;
        ar[DIM + d] = hi;
        ar[2 * DIM + d] = lo;
    }
}

// ---------------------------------------------------------------------------
// Kernel 2: gather w[:, sampled] -> bf16 split layout [hi | lo | hi], + soff
// ---------------------------------------------------------------------------
__global__ void gather_b_kernel(const float* __restrict__ w,
                                const float* __restrict__ b,
                                const int* __restrict__ sampled) {
    int s = blockIdx.x;
    __nv_bfloat16* br = g_b + (size_t)s * KTOT;
    if (s < NS) {
        int c = sampled[s];
        const float* wc = w + c;
        for (int d = threadIdx.x; d < DIM; d += 256) {
            float v = wc[(size_t)d * NC];
            __nv_bfloat16 hi = __float2bfloat16(v);
            __nv_bfloat16 lo = __float2bfloat16(v - __bfloat162float(hi));
            br[d] = hi;
            br[DIM + d] = lo;
            br[2 * DIM + d] = hi;
        }
        if (threadIdx.x == 0)
            g_soff[s] = b[c] - log_expected_count(c);
    } else {
        __nv_bfloat16 z = __float2bfloat16(0.0f);
        for (int d = threadIdx.x; d < KTOT; d += 256)
            br[d] = z;
        if (threadIdx.x == 0)
            g_soff[s] = 0.0f;
    }
}

// ---------------------------------------------------------------------------
// Kernel 3: true logits (fp32 warp-dot) + seed true exp-term
// ---------------------------------------------------------------------------
__global__ void true_kernel(const float* __restrict__ x,
                            const float* __restrict__ w,
                            const float* __restrict__ b,
                            const int* __restrict__ labels) {
    int r = blockIdx.x * 8 + (threadIdx.x >> 5);
    int lane = threadIdx.x & 31;
    if (r >= BATCH) return;
    int c = labels[r];
    const float* xr = x + (size_t)r * DIM;
    const float* wc = w + c;
    float s = 0.0f;
    for (int d = lane; d < DIM; d += 32)
        s += xr[d] * wc[(size_t)d * NC];
    #pragma unroll
    for (int o = 16; o; o >>= 1)
        s += __shfl_xor_sync(0xffffffffu, s, o);
    if (lane == 0) {
        float t = s + b[c] - log_expected_count(c);
        g_true[r] = t;
        g_partial[r * NSLOT + NSLOT - 1] = expf(t - LSE_OFF);
    }
}

// ---------------------------------------------------------------------------
// Kernel 4: bf16 mma.sync GEMM 128x128x(3072), fused exp-sum epilogue
// SMEM: A[2][16KB] at 0, B[2][16KB] at 32768, soff(512B) at 65536
// ---------------------------------------------------------------------------
#define SM_A 0
#define SM_B 32768
#define SM_SOFF 65536
#define SM_TOTAL (SM_SOFF + TN * 4)

__global__ __launch_bounds__(256, 2)
void gemm_lse_kernel() {
    extern __shared__ char smem[];
    const uint32_t sbase = smem_u32(smem);
    float* soff_s = (float*)(smem + SM_SOFF);

    int tid = threadIdx.x;
    int lane = tid & 31;
    int wid = tid >> 5;
    int wm = wid & 1;          // 2 m-warps (64 rows each)
    int wn = wid >> 1;         // 4 n-warps (32 cols each)
    int bn = blockIdx.x;
    int bm = blockIdx.y;
    int m0 = bm * TM;
    int n0 = bn * TN;

    const __nv_bfloat16* ga = g_a + (size_t)m0 * KTOT;
    const __nv_bfloat16* gb = g_b + (size_t)n0 * KTOT;

    if (tid < TN) soff_s[tid] = g_soff[n0 + tid];

    // Per-thread load slots (4 chunks A + 4 chunks B per iter)
    int lrow = tid >> 3;            // 0..31 (+32 per i)
    int lc   = tid & 7;             // chunk 0..7

    float acc[4][4][4];
    #pragma unroll
    for (int i = 0; i < 4; i++)
        #pragma unroll
        for (int j = 0; j < 4; j++)
            #pragma unroll
            for (int v = 0; v < 4; v++) acc[i][j][v] = 0.0f;

    // Prologue: load tile 0
    #pragma unroll
    for (int i = 0; i < 4; i++) {
        int row = lrow + i * 32;
        uint32_t sw = (uint32_t)(row * 128 + ((lc ^ (row & 7)) * 16));
        CP_ASYNC16(sbase + SM_A + sw, ga + (size_t)row * KTOT + lc * 8);
        CP_ASYNC16(sbase + SM_B + sw, gb + (size_t)row * KTOT + lc * 8);
    }
    CP_COMMIT();

    for (int it = 0; it < NKT; it++) {
        int buf = it & 1;
        if (it + 1 < NKT) {
            int kk = (it + 1) * TK;
            uint32_t boff = (uint32_t)((buf ^ 1) * 16384);
            #pragma unroll
            for (int i = 0; i < 4; i++) {
                int row = lrow + i * 32;
                uint32_t sw = boff + (uint32_t)(row * 128 + ((lc ^ (row & 7)) * 16));
                CP_ASYNC16(sbase + SM_A + sw, ga + (size_t)row * KTOT + kk + lc * 8);
                CP_ASYNC16(sbase + SM_B + sw, gb + (size_t)row * KTOT + kk + lc * 8);
            }
            CP_COMMIT();
            CP_WAIT1();
        } else {
            CP_WAIT0();
        }
        __syncthreads();

        uint32_t abase = sbase + SM_A + buf * 16384;
        uint32_t bbase = sbase + SM_B + buf * 16384;
        int mat = lane >> 3;
        int lr8 = lane & 7;

        #pragma unroll
        for (int ks = 0; ks < 4; ks++) {
            int c = 2 * ks;
            uint32_t a[4][4], bfr[4][2];
            #pragma unroll
            for (int i = 0; i < 4; i++) {
                int r = wm * 64 + i * 16 + lr8 + ((mat & 1) << 3);
                int cc = c + (mat >> 1);
                uint32_t addr = abase + (uint32_t)(r * 128 + ((cc ^ (r & 7)) * 16));
                LDSM_X4(a[i][0], a[i][1], a[i][2], a[i][3], addr);
            }
            #pragma unroll
            for (int p = 0; p < 2; p++) {
                int r = wn * 32 + p * 16 + lr8 + ((mat & 1) << 3);
                int cc = c + (mat >> 1);
                uint32_t addr = bbase + (uint32_t)(r * 128 + ((cc ^ (r & 7)) * 16));
                uint32_t t0, t1, t2, t3;
                LDSM_X4(t0, t1, t2, t3, addr);
                bfr[2 * p][0] = t0; bfr[2 * p][1] = t2;
                bfr[2 * p + 1][0] = t1; bfr[2 * p + 1][1] = t3;
            }
            #pragma unroll
            for (int i = 0; i < 4; i++)
                #pragma unroll
                for (int j = 0; j < 4; j++)
                    MMA16816(acc[i][j], a[i], bfr[j]);
        }
        __syncthreads();
    }

    // Fused epilogue: exp-sum per row with n<NS mask and column offsets
    float sr0[4], sr1[4];
    #pragma unroll
    for (int i = 0; i < 4; i++) { sr0[i] = 0.0f; sr1[i] = 0.0f; }

    #pragma unroll
    for (int j = 0; j < 4; j++) {
        int l = wn * 32 + j * 8 + 2 * (lane & 3);
        int gn = n0 + l;
        float o0 = soff_s[l] - LSE_OFF;
        float o1 = soff_s[l + 1] - LSE_OFF;
        bool v0 = gn < NS;
        bool v1 = (gn + 1) < NS;
        #pragma unroll
        for (int i = 0; i < 4; i++) {
            if (v0) sr0[i] += expf(acc[i][j][0] + o0);
            if (v1) sr0[i] += expf(acc[i][j][1] + o1);
            if (v0) sr1[i] += expf(acc[i][j][2] + o0);
            if (v1) sr1[i] += expf(acc[i][j][3] + o1);
        }
    }
    #pragma unroll
    for (int i = 0; i < 4; i++) {
        sr0[i] += __shfl_xor_sync(0xffffffffu, sr0[i], 1);
        sr0[i] += __shfl_xor_sync(0xffffffffu, sr0[i], 2);
        sr1[i] += __shfl_xor_sync(0xffffffffu, sr1[i], 1);
        sr1[i] += __shfl_xor_sync(0xffffffffu, sr1[i], 2);
    }
    if ((lane & 3) == 0) {
        int slot = bn * 4 + wn;
        #pragma unroll
        for (int i = 0; i < 4; i++) {
            int r0 = m0 + wm * 64 + i * 16 + (lane >> 2);
            g_partial[r0 * NSLOT + slot] = sr0[i];
            g_partial[(r0 + 8) * NSLOT + slot] = sr1[i];
        }
    }
}

// ---------------------------------------------------------------------------
// Kernel 5/6: final reduction (parallel, deterministic)
// ---------------------------------------------------------------------------
__global__ void final_partial_kernel() {
    __shared__ float red[128];
    int r = blockIdx.x * 128 + threadIdx.x;
    float s = 0.0f;
    #pragma unroll 8
    for (int t = 0; t < NSLOT; t++)
        s += g_partial[r * NSLOT + t];
    float acc = LSE_OFF + logf(s) - g_true[r];
    red[threadIdx.x] = acc;
    __syncthreads();
    for (int st = 64; st; st >>= 1) {
        if (threadIdx.x < st) red[threadIdx.x] += red[threadIdx.x + st];
        __syncthreads();
    }
    if (threadIdx.x == 0)
        g_fin[blockIdx.x] = red[0];
}

__global__ void final_sum_kernel(float* __restrict__ out) {
    float v = g_fin[threadIdx.x];
    #pragma unroll
    for (int o = 16; o; o >>= 1)
        v += __shfl_xor_sync(0xffffffffu, v, o);
    if (threadIdx.x == 0)
        out[0] = v / (float)BATCH;
}

// ---------------------------------------------------------------------------
extern "C" void kernel_launch(void* const* d_in, const int* in_sizes, int n_in,
                              void* d_out, int out_size) {
    const float* x       = (const float*)d_in[0];
    const float* w       = (const float*)d_in[1];
    const float* b       = (const float*)d_in[2];
    const int*   labels  = (const int*)d_in[3];
    const int*   sampled = (const int*)d_in[4];
    float* out = (float*)d_out;

    cudaFuncSetAttribute(gemm_lse_kernel,
                         cudaFuncAttributeMaxDynamicSharedMemorySize, SM_TOTAL);

    convert_x_kernel<<<BATCH, 256>>>(x);
    gather_b_kernel<<<NS_PAD, 256>>>(w, b, sampled);
    true_kernel<<<BATCH / 8, 256>>>(x, w, b, labels);
    dim3 grid(NTN, BATCH / TM);
    gemm_lse_kernel<<<grid, 256, SM_TOTAL>>>();
    final_partial_kernel<<<32, 128>>>();
    final_sum_kernel<<<1, 32>>>(out);
}